// round 11
// baseline (speedup 1.0000x reference)
#include <cuda_runtime.h>
#include <cuda_fp16.h>
#include <math.h>
#include <stdint.h>

// Problem constants
#define T_     128
#define NSEQ   256          // B*S
#define EMBED  512
#define UNITS  512
#define G4     2048         // 4*UNITS
#define NZ     4096         // both directions
#define NCTA   128
#define GSZ    16           // CTAs per dependency group (dir, rb)

// ---------------- scratch (device globals) ---------------------------------
// xW packed per dir as [hcol*4 + gate] (gates adjacent -> uint4 per 2 hcols)
__device__ __half   g_xW[(size_t)NSEQ * T_ * NZ];
__device__ __half   g_h16[2][2][NSEQ * UNITS];     // fp16 h, [parity][dir]
__device__ uint32_t g_Upk[2 * 16 * 32768];         // fp16 frag-packed U per (dir,cb) slice
__device__ uint32_t g_Wpk[32 * 32768];             // fp16 frag-packed [W_f|W_b]

struct alignas(128) Bar { unsigned cnt; unsigned gen; };
__device__ Bar g_bars[8];                          // one per (dir, rb) group

__device__ __forceinline__ float tanh_fast(float x) {
    float r; asm("tanh.approx.f32 %0, %1;" : "=f"(r) : "f"(x)); return r;
}
__device__ __forceinline__ float sigm_fast(float x) {
    return fmaf(tanh_fast(0.5f * x), 0.5f, 0.5f);
}

// ---------------- pack U into fp16 mma.sync fragment order -----------------
// Slice (dir, cb): B[k][n] = U[k][g*512 + cb*32 + hl], n = g*32+hl (128 zcols).
// Word layout: [kb 32][np 8][lane 32][4 words]; word (sub*2+wi) holds
// k = kb*16 + wi*8 + 2qc (+1), n = (np*2+sub)*8 + qr. lane = qr*4+qc.
__global__ __launch_bounds__(256) void prep_U(
    const float* __restrict__ U_f, const float* __restrict__ U_b)
{
    int widx  = blockIdx.x * 256 + threadIdx.x;   // < 2^20
    int word  = widx & 32767;
    int slice = widx >> 15;
    int dir = slice >> 4, cb = slice & 15;
    int kb   = word >> 10;
    int np   = (word >> 7) & 7;
    int lane = (word >> 2) & 31;
    int q    = word & 3;
    int sub = q >> 1, wi = q & 1;
    int qr = lane >> 2, qc = lane & 3;
    int n = (np * 2 + sub) * 8 + qr;
    int k = kb * 16 + wi * 8 + 2 * qc;
    int col = (n >> 5) * 512 + cb * 32 + (n & 31);
    const float* U = dir ? U_b : U_f;
    float lo = U[(size_t)k * G4 + col];
    float hi = U[(size_t)(k + 1) * G4 + col];
    half2 h2 = __floats2half2_rn(lo, hi);
    g_Upk[widx] = *(uint32_t*)&h2;
}

// ---------------- pack [W_f|W_b] into same fragment order ------------------
__global__ __launch_bounds__(256) void prep_W(
    const float* __restrict__ W_f, const float* __restrict__ W_b)
{
    int widx  = blockIdx.x * 256 + threadIdx.x;
    int word  = widx & 32767;
    int nb    = widx >> 15;
    int kb   = word >> 10;
    int np   = (word >> 7) & 7;
    int lane = (word >> 2) & 31;
    int q    = word & 3;
    int sub = q >> 1, wi = q & 1;
    int qr = lane >> 2, qc = lane & 3;
    int nl = (np * 2 + sub) * 8 + qr;
    int k  = kb * 16 + wi * 8 + 2 * qc;
    int c  = nb * 128 + nl;
    const float* W = (c < G4) ? (W_f + c) : (W_b + c - G4);
    float lo = W[(size_t)k * G4];
    float hi = W[(size_t)(k + 1) * G4];
    half2 h2 = __floats2half2_rn(lo, hi);
    g_Wpk[widx] = *(uint32_t*)&h2;
}

// ---------------- MMA helpers ----------------------------------------------
#define MMA16816(d, a, b0v, b1v)                                              \
    asm volatile(                                                             \
        "mma.sync.aligned.m16n8k16.row.col.f32.f16.f16.f32 "                  \
        "{%0,%1,%2,%3},{%4,%5,%6,%7},{%8,%9},{%0,%1,%2,%3};"                  \
        : "+f"(d[0]), "+f"(d[1]), "+f"(d[2]), "+f"(d[3])                      \
        : "r"(a[0]), "r"(a[1]), "r"(a[2]), "r"(a[3]), "r"(b0v), "r"(b1v))

#define LDSM4(r, addr)                                                        \
    asm volatile("ldmatrix.sync.aligned.m8n8.x4.shared.b16 "                  \
                 "{%0,%1,%2,%3}, [%4];"                                       \
                 : "=r"(r[0]), "=r"(r[1]), "=r"(r[2]), "=r"(r[3])             \
                 : "r"(addr))

extern __shared__ char smem_dyn[];

// ---------------- Phase 1: fused gather + fp16 tensor-core GEMM ------------
#define ESTR 520

__global__ __launch_bounds__(256, 1) void embed_mma(
    const int* __restrict__ x, const float* __restrict__ emb,
    const float* __restrict__ b_f, const float* __restrict__ b_b)
{
    __shared__ int ids_s[128];
    __half* hA = (__half*)smem_dyn;

    const int tid  = threadIdx.x;
    const int lane = tid & 31;
    const int wid  = tid >> 5;
    const int wm   = wid >> 1;
    const int wn   = wid & 1;
    const int qr = lane >> 2, qc = lane & 3;
    const int mBase = blockIdx.y * 128;
    const int nb    = blockIdx.x * 2 + wn;

    if (tid < 128) ids_s[tid] = x[mBase + tid];
    __syncthreads();

    {
        int row = tid >> 1, seg = tid & 1;
        const float* src = emb + (size_t)ids_s[row] * EMBED + seg * 256;
        __half* d = hA + row * ESTR + seg * 256;
        #pragma unroll
        for (int i = 0; i < 64; i++) {
            float4 v = *(const float4*)(src + i * 4);
            *(half2*)(d + i * 4)     = __floats2half2_rn(v.x, v.y);
            *(half2*)(d + i * 4 + 2) = __floats2half2_rn(v.z, v.w);
        }
    }
    __syncthreads();

    int lm_row = (lane & 7) + ((lane >> 3) & 1) * 8;
    int lm_kh  = (lane >> 4) * 8;
    uint32_t hA_s = (uint32_t)__cvta_generic_to_shared(hA);
    uint32_t lmaddr0 = hA_s + (uint32_t)(((wm * 32 + 0  + lm_row) * ESTR + lm_kh) * 2);
    uint32_t lmaddr1 = hA_s + (uint32_t)(((wm * 32 + 16 + lm_row) * ESTR + lm_kh) * 2);

    const uint32_t* gW = g_Wpk + (size_t)nb * 32768;

    float acc[2][16][4];
    #pragma unroll
    for (int mt = 0; mt < 2; mt++)
        #pragma unroll
        for (int j = 0; j < 16; j++)
            #pragma unroll
            for (int r = 0; r < 4; r++) acc[mt][j][r] = 0.f;

    #pragma unroll 2
    for (int kb = 0; kb < 32; kb++) {
        uint32_t a0[4], a1[4];
        LDSM4(a0, lmaddr0 + kb * 32);
        LDSM4(a1, lmaddr1 + kb * 32);
        uint4 Bv[8];
        #pragma unroll
        for (int np = 0; np < 8; np++)
            Bv[np] = *(const uint4*)&gW[(((kb * 8 + np) * 32 + lane) << 2)];
        #pragma unroll
        for (int j = 0; j < 16; j++) {
            uint32_t b0 = (j & 1) ? Bv[j >> 1].z : Bv[j >> 1].x;
            uint32_t b1 = (j & 1) ? Bv[j >> 1].w : Bv[j >> 1].y;
            MMA16816(acc[0][j], a0, b0, b1);
            MMA16816(acc[1][j], a1, b0, b1);
        }
    }

    // Epilogue: add bias, store fp16 z packed as [hcol*4 + gate]
    const float* bp = (nb < 16) ? (b_f + nb * 128) : (b_b + nb * 128 - G4);
    const int dirW = nb >> 4;
    const int nOff = (nb & 15) * 128;
    #pragma unroll
    for (int mt = 0; mt < 2; mt++) {
        #pragma unroll
        for (int j = 0; j < 16; j++) {
            int row = mBase + wm * 32 + mt * 16 + qr;
            int cl  = j * 8 + qc * 2;
            int n0  = nOff + cl;
            int g0  = n0 >> 9, h0 = n0 & 511;
            float bx = bp[cl], by = bp[cl + 1];
            size_t pk0 = (size_t)dirW * 2048 + h0 * 4 + g0;
            g_xW[(size_t)row * NZ + pk0]           = __float2half(acc[mt][j][0] + bx);
            g_xW[(size_t)row * NZ + pk0 + 4]       = __float2half(acc[mt][j][1] + by);
            g_xW[(size_t)(row + 8) * NZ + pk0]     = __float2half(acc[mt][j][2] + bx);
            g_xW[(size_t)(row + 8) * NZ + pk0 + 4] = __float2half(acc[mt][j][3] + by);
        }
    }
}

// ---------------- Phase 2: persistent bidirectional LSTM -------------------
// 128 CTAs x 512 thr. bid = gid*16 + cb, gid = dir*4 + rb.
// Decentralized group barrier (all-thread poll, gen0-relative target);
// per-wm-group private staging + named bar.sync; register state; MUFU epi.
__global__ __launch_bounds__(512, 1) void lstm_persist(
    const int* __restrict__ x, float* __restrict__ out)
{
    uint32_t* uB  = (uint32_t*)smem_dyn;           // 128 KB
    char*     hAb = smem_dyn + 131072;             // 64 KB swizzled A staging

    const int tid  = threadIdx.x;
    const int lane = tid & 31;
    const int wid  = tid >> 5;                     // 0..15
    const int bid  = blockIdx.x;
    const int gid  = bid >> 4;                     // 0..7
    const int dir  = gid >> 2;
    const int rb   = gid & 3;
    const int cb   = bid & 15;
    const int rBase  = rb * 64;
    const int cbBase = cb * 32;

    // Load U slice once (resident for all steps)
    {
        const uint4* src = (const uint4*)(g_Upk + (size_t)(dir * 16 + cb) * 32768);
        uint4* dst = (uint4*)uB;
        #pragma unroll
        for (int i = 0; i < 16; i++) dst[i * 512 + tid] = src[i * 512 + tid];
    }

    const int wm = wid >> 2;          // 0..3 : 16 rows
    const int wn = wid & 3;           // 0..3 : 8 hcols each
    const int qr = lane >> 2, qc = lane & 3;
    const int woff = wn >> 1;
    const int sub2 = (wn & 1) * 2;
    const int hc = wn * 8 + 2 * qc;   // local hcol (even)

    // Register-resident state
    float creg[4], hreg[4];
    #pragma unroll
    for (int e = 0; e < 4; e++) { creg[e] = 0.f; hreg[e] = 0.f; }
    // Zero own h16[0] slice: 64 rows x 32 cols fp16
    {
        int row = rBase + (tid >> 3);
        int seg = (tid & 7) * 4;
        *(uint2*)&g_h16[0][dir][row * UNITS + cbBase + seg] = make_uint2(0, 0);
    }

    // ldmatrix swizzled base: addr(kb) = C0 ^ (kb*32)
    const int lrow = wm * 16 + (lane & 7) + ((lane >> 3) & 1) * 8;
    const int hi   = lane >> 4;
    const int r7   = lrow & 7;
    uint32_t hA_s = (uint32_t)__cvta_generic_to_shared(hAb);
    const uint32_t C0 = hA_s + (uint32_t)(lrow * 1024 + ((hi ^ (r7 & 1)) * 16) + (r7 >> 1) * 32);

    // Private staging: warp (wm, wn) stages local rows wm*16 + wn*4 + (lane>>3)
    const int slrow = wm * 16 + wn * 4 + (lane >> 3);
    const int sc8   = lane & 7;
    const int sr7   = slrow & 7;

    // Snapshot barrier generation (stable: flip requires this CTA's arrive)
    volatile unsigned* genp = &g_bars[gid].gen;
    const unsigned gen0 = *genp;

    uint4 xv[2];
    bool  mreg[2];

    for (int sstep = 0; sstep < T_; sstep++) {
        const int parity = sstep & 1;
        const int t = dir ? (T_ - 1 - sstep) : sstep;
        const __half* h16cur = g_h16[parity][dir];
        __half*       h16nxt = g_h16[parity ^ 1][dir];

        // ---- prefetch xW (one uint4 = 2 hcols x 4 gates) + mask ----
        #pragma unroll
        for (int e = 0; e < 2; e++) {
            int s = rBase + wm * 16 + qr + e * 8;
            xv[e] = __ldcs((const uint4*)(g_xW + ((size_t)s * T_ + t) * NZ
                                          + dir * 2048 + (size_t)(cbBase + hc) * 4));
            mreg[e] = (x[s * T_ + t] != 0);
        }

        // ---- barrier arrive: all warps of CTA done publishing prev h ----
        __syncthreads();
        if (tid == 0) {
            __threadfence();
            if (atomicAdd(&g_bars[gid].cnt, 1u) == GSZ - 1) {
                g_bars[gid].cnt = 0;
                __threadfence();
                *genp = gen0 + (unsigned)sstep + 1u;
            }
        }

        // ---- barrier wait: every thread polls (warp-level resume) ----
        {
            const unsigned tgt = gen0 + (unsigned)sstep + 1u;
            while ((int)(*genp - tgt) < 0) { __nanosleep(32); }
            __threadfence();
        }

        // ---- stage own 4 rows -> swizzled SMEM (private per wm group) ----
        {
            const __half* src = h16cur + (size_t)(rBase + slrow) * UNITS;
            #pragma unroll
            for (int i = 0; i < 8; i++) {
                int u = i * 8 + sc8;
                uint4 v = *(const uint4*)(src + u * 8);
                *(uint4*)(hAb + slrow * 1024 + ((u ^ sr7) * 16)) = v;
            }
        }
        asm volatile("bar.sync %0, %1;" :: "r"(wm + 1), "r"(128) : "memory");

        // ---- K loop: z = h @ U, software-pipelined ----
        float acc[4][4];
        #pragma unroll
        for (int g = 0; g < 4; g++)
            #pragma unroll
            for (int r = 0; r < 4; r++) acc[g][r] = 0.f;

        uint32_t aP[4];
        uint2    bP[4];
        LDSM4(aP, C0);
        #pragma unroll
        for (int g = 0; g < 4; g++)
            bP[g] = *(const uint2*)&uB[(((g * 2 + woff) * 32 + lane) << 2) + sub2];

        #pragma unroll
        for (int kb = 0; kb < 32; kb++) {
            uint32_t aC[4] = { aP[0], aP[1], aP[2], aP[3] };
            uint2    bC[4] = { bP[0], bP[1], bP[2], bP[3] };
            if (kb + 1 < 32) {
                LDSM4(aP, C0 ^ (uint32_t)((kb + 1) << 5));
                #pragma unroll
                for (int g = 0; g < 4; g++)
                    bP[g] = *(const uint2*)&uB[((((kb + 1) * 8 + g * 2 + woff) * 32 + lane) << 2) + sub2];
            }
            #pragma unroll
            for (int g = 0; g < 4; g++)
                MMA16816(acc[g], aC, bC[g].x, bC[g].y);
        }

        // ---- fused gate epilogue on registers; publish h fp16 ----
        #pragma unroll
        for (int e = 0; e < 2; e++) {
            const half2* ph = (const half2*)&xv[e];
            float hv[2];
            #pragma unroll
            for (int cc = 0; cc < 2; cc++) {
                int idx = e * 2 + cc;
                float2 p0 = __half22float2(ph[cc * 2]);
                float2 p1 = __half22float2(ph[cc * 2 + 1]);
                float zi = acc[0][idx] + p0.x;
                float zf = acc[1][idx] + p0.y;
                float zg = acc[2][idx] + p1.x;
                float zo = acc[3][idx] + p1.y;
                float ig = sigm_fast(zi), fg = sigm_fast(zf);
                float gg = tanh_fast(zg), og = sigm_fast(zo);
                float cnew = fg * creg[idx] + ig * gg;
                float hnew = og * tanh_fast(cnew);
                if (mreg[e]) { creg[idx] = cnew; hreg[idx] = hnew; }
                hv[cc] = hreg[idx];
            }
            int row = rBase + wm * 16 + qr + e * 8;
            *(half2*)&h16nxt[row * UNITS + cbBase + hc] = __floats2half2_rn(hv[0], hv[1]);
        }
    }

    // Output straight from registers
    #pragma unroll
    for (int e = 0; e < 2; e++) {
        int s = rBase + wm * 16 + qr + e * 8;
        *(float2*)&out[s * 1024 + dir * 512 + cbBase + hc] =
            make_float2(hreg[e * 2], hreg[e * 2 + 1]);
    }
}

// ---------------- launcher -------------------------------------------------
extern "C" void kernel_launch(void* const* d_in, const int* in_sizes, int n_in,
                              void* d_out, int out_size)
{
    const int*   x   = (const int*)  d_in[0];
    const float* emb = (const float*)d_in[1];
    const float* W_f = (const float*)d_in[2];
    const float* U_f = (const float*)d_in[3];
    const float* b_f = (const float*)d_in[4];
    const float* W_b = (const float*)d_in[5];
    const float* U_b = (const float*)d_in[6];
    const float* b_b = (const float*)d_in[7];
    float* out = (float*)d_out;

    cudaFuncSetAttribute(embed_mma,
                         cudaFuncAttributeMaxDynamicSharedMemorySize, 133120);
    cudaFuncSetAttribute(lstm_persist,
                         cudaFuncAttributeMaxDynamicSharedMemorySize, 196608);

    prep_U<<<(2 * 16 * 32768) / 256, 256>>>(U_f, U_b);
    prep_W<<<(32 * 32768) / 256, 256>>>(W_f, W_b);
    embed_mma<<<dim3(16, 256), 256, 133120>>>(x, emb, b_f, b_b);
    lstm_persist<<<NCTA, 512, 196608>>>(x, out);
}

// round 12
// speedup vs baseline: 1.2754x; 1.2754x over previous
#include <cuda_runtime.h>
#include <cuda_fp16.h>
#include <math.h>
#include <stdint.h>

// Problem constants
#define T_     128
#define NSEQ   256          // B*S
#define EMBED  512
#define UNITS  512
#define G4     2048         // 4*UNITS
#define NZ     4096         // both directions
#define NCTA   128
#define GSZ    16           // CTAs per dependency group (dir, rb)

// ---------------- scratch (device globals) ---------------------------------
__device__ __half   g_xW[(size_t)NSEQ * T_ * NZ];  // fp16 [s*T+t][4096] fwd|bwd, bias incl
__device__ __half   g_h16[2][2][NSEQ * UNITS];     // fp16 h, [parity][dir]
__device__ uint32_t g_Upk[2 * 16 * 32768];         // fp16 frag-packed U per (dir,cb) slice
__device__ uint32_t g_Wpk[32 * 32768];             // fp16 frag-packed [W_f|W_b]

struct alignas(128) Bar { unsigned cnt; unsigned gen; };
__device__ Bar g_bars[8];                          // one per (dir, rb) group

__device__ __forceinline__ float tanh_fast(float x) {
    float r; asm("tanh.approx.f32 %0, %1;" : "=f"(r) : "f"(x)); return r;
}
__device__ __forceinline__ float sigm_fast(float x) {
    return fmaf(tanh_fast(0.5f * x), 0.5f, 0.5f);
}

// ---------------- pack U into fp16 mma.sync fragment order -----------------
// Slice (dir, cb): B[k][n] = U[k][g*512 + cb*32 + hl], n = g*32+hl (128 zcols).
__global__ __launch_bounds__(256) void prep_U(
    const float* __restrict__ U_f, const float* __restrict__ U_b)
{
    int widx  = blockIdx.x * 256 + threadIdx.x;   // < 2^20
    int word  = widx & 32767;
    int slice = widx >> 15;
    int dir = slice >> 4, cb = slice & 15;
    int kb   = word >> 10;
    int np   = (word >> 7) & 7;
    int lane = (word >> 2) & 31;
    int q    = word & 3;
    int sub = q >> 1, wi = q & 1;
    int qr = lane >> 2, qc = lane & 3;
    int n = (np * 2 + sub) * 8 + qr;
    int k = kb * 16 + wi * 8 + 2 * qc;
    int col = (n >> 5) * 512 + cb * 32 + (n & 31);
    const float* U = dir ? U_b : U_f;
    float lo = U[(size_t)k * G4 + col];
    float hi = U[(size_t)(k + 1) * G4 + col];
    half2 h2 = __floats2half2_rn(lo, hi);
    g_Upk[widx] = *(uint32_t*)&h2;
}

// ---------------- pack [W_f|W_b] into same fragment order ------------------
__global__ __launch_bounds__(256) void prep_W(
    const float* __restrict__ W_f, const float* __restrict__ W_b)
{
    int widx  = blockIdx.x * 256 + threadIdx.x;
    int word  = widx & 32767;
    int nb    = widx >> 15;
    int kb   = word >> 10;
    int np   = (word >> 7) & 7;
    int lane = (word >> 2) & 31;
    int q    = word & 3;
    int sub = q >> 1, wi = q & 1;
    int qr = lane >> 2, qc = lane & 3;
    int nl = (np * 2 + sub) * 8 + qr;
    int k  = kb * 16 + wi * 8 + 2 * qc;
    int c  = nb * 128 + nl;
    const float* W = (c < G4) ? (W_f + c) : (W_b + c - G4);
    float lo = W[(size_t)k * G4];
    float hi = W[(size_t)(k + 1) * G4];
    half2 h2 = __floats2half2_rn(lo, hi);
    g_Wpk[widx] = *(uint32_t*)&h2;
}

// ---------------- MMA helpers ----------------------------------------------
#define MMA16816(d, a, b0v, b1v)                                              \
    asm volatile(                                                             \
        "mma.sync.aligned.m16n8k16.row.col.f32.f16.f16.f32 "                  \
        "{%0,%1,%2,%3},{%4,%5,%6,%7},{%8,%9},{%0,%1,%2,%3};"                  \
        : "+f"(d[0]), "+f"(d[1]), "+f"(d[2]), "+f"(d[3])                      \
        : "r"(a[0]), "r"(a[1]), "r"(a[2]), "r"(a[3]), "r"(b0v), "r"(b1v))

#define LDSM4(r, addr)                                                        \
    asm volatile("ldmatrix.sync.aligned.m8n8.x4.shared.b16 "                  \
                 "{%0,%1,%2,%3}, [%4];"                                       \
                 : "=r"(r[0]), "=r"(r[1]), "=r"(r[2]), "=r"(r[3])             \
                 : "r"(addr))

extern __shared__ char smem_dyn[];

// ---------------- Phase 1: fused gather + fp16 GEMM, A staged ONCE ---------
// 256 CTAs (one per 128-row block) x 256 thr. A (128x512 fp16) staged once;
// loop over 16 nb-pair slices (each warp-column handles one nb per iter).
#define ESTR 520

__global__ __launch_bounds__(256, 1) void embed_mma(
    const int* __restrict__ x, const float* __restrict__ emb,
    const float* __restrict__ b_f, const float* __restrict__ b_b)
{
    __shared__ int ids_s[128];
    __half* hA = (__half*)smem_dyn;                // 128 x ESTR halves

    const int tid  = threadIdx.x;
    const int lane = tid & 31;
    const int wid  = tid >> 5;
    const int wm   = wid >> 1;          // 0..3 : 32 rows
    const int wn   = wid & 1;           // 0..1 : which nb of the pair
    const int qr = lane >> 2, qc = lane & 3;
    const int mBase = blockIdx.x * 128;

    if (tid < 128) ids_s[tid] = x[mBase + tid];
    __syncthreads();

    // Stage full A tile once: 128 rows x 512 k, fp32 -> fp16
    {
        int row = tid >> 1, seg = tid & 1;
        const float* src = emb + (size_t)ids_s[row] * EMBED + seg * 256;
        __half* d = hA + row * ESTR + seg * 256;
        #pragma unroll
        for (int i = 0; i < 64; i++) {
            float4 v = *(const float4*)(src + i * 4);
            *(half2*)(d + i * 4)     = __floats2half2_rn(v.x, v.y);
            *(half2*)(d + i * 4 + 2) = __floats2half2_rn(v.z, v.w);
        }
    }
    __syncthreads();

    int lm_row = (lane & 7) + ((lane >> 3) & 1) * 8;
    int lm_kh  = (lane >> 4) * 8;
    uint32_t hA_s = (uint32_t)__cvta_generic_to_shared(hA);
    uint32_t lmaddr0 = hA_s + (uint32_t)(((wm * 32 + 0  + lm_row) * ESTR + lm_kh) * 2);
    uint32_t lmaddr1 = hA_s + (uint32_t)(((wm * 32 + 16 + lm_row) * ESTR + lm_kh) * 2);

    for (int it = 0; it < 16; it++) {
        const int nb = it * 2 + wn;
        const uint32_t* gW = g_Wpk + (size_t)nb * 32768;

        float acc[2][16][4];
        #pragma unroll
        for (int mt = 0; mt < 2; mt++)
            #pragma unroll
            for (int j = 0; j < 16; j++)
                #pragma unroll
                for (int r = 0; r < 4; r++) acc[mt][j][r] = 0.f;

        #pragma unroll 2
        for (int kb = 0; kb < 32; kb++) {
            uint32_t a0[4], a1[4];
            LDSM4(a0, lmaddr0 + kb * 32);
            LDSM4(a1, lmaddr1 + kb * 32);
            uint4 Bv[8];
            #pragma unroll
            for (int np = 0; np < 8; np++)
                Bv[np] = *(const uint4*)&gW[(((kb * 8 + np) * 32 + lane) << 2)];
            #pragma unroll
            for (int j = 0; j < 16; j++) {
                uint32_t b0 = (j & 1) ? Bv[j >> 1].z : Bv[j >> 1].x;
                uint32_t b1 = (j & 1) ? Bv[j >> 1].w : Bv[j >> 1].y;
                MMA16816(acc[0][j], a0, b0, b1);
                MMA16816(acc[1][j], a1, b0, b1);
            }
        }

        // Epilogue: add bias, coalesced half2 stores (R7 layout)
        const float* bp = (nb < 16) ? (b_f + nb * 128) : (b_b + nb * 128 - G4);
        #pragma unroll
        for (int mt = 0; mt < 2; mt++) {
            #pragma unroll
            for (int j = 0; j < 16; j++) {
                int row = mBase + wm * 32 + mt * 16 + qr;
                int cl  = j * 8 + qc * 2;
                float bx = bp[cl], by = bp[cl + 1];
                half2 lo = __floats2half2_rn(acc[mt][j][0] + bx, acc[mt][j][1] + by);
                half2 hi = __floats2half2_rn(acc[mt][j][2] + bx, acc[mt][j][3] + by);
                *(half2*)&g_xW[(size_t)row * NZ + nb * 128 + cl]       = lo;
                *(half2*)&g_xW[(size_t)(row + 8) * NZ + nb * 128 + cl] = hi;
            }
        }
    }
}

// ---------------- Phase 2: persistent bidirectional LSTM (R7, verbatim) ----
// 128 CTAs x 512 thr. CTA (dir, cb, rb): 64 rows x 128 zcols.
// Warp (wm 0..3, wn 0..3): 16 rows x 32 zcols (wn = gate). 16-CTA group sync.
#define ZSTR 132   // z exchange row stride in floats

__global__ __launch_bounds__(512, 1) void lstm_persist(
    const int* __restrict__ x, float* __restrict__ out)
{
    uint32_t* uB  = (uint32_t*)smem_dyn;           // 128 KB
    char*     hAb = smem_dyn + 131072;             // 64 KB swizzled A staging
    float*    shZ = (float*)(smem_dyn + 131072);   // alias (post-sync)

    const int tid  = threadIdx.x;
    const int lane = tid & 31;
    const int wid  = tid >> 5;                     // 0..15
    const int bid  = blockIdx.x;
    const int dir  = bid >> 6;
    const int cb   = (bid >> 2) & 15;
    const int rb   = bid & 3;
    const int gid  = dir * 4 + rb;
    const int rBase  = rb * 64;
    const int cbBase = cb * 32;

    // Load U slice once (resident for all steps)
    {
        const uint4* src = (const uint4*)(g_Upk + (size_t)(dir * 16 + cb) * 32768);
        uint4* dst = (uint4*)uB;
        #pragma unroll
        for (int i = 0; i < 16; i++) dst[i * 512 + tid] = src[i * 512 + tid];
    }

    // Register-resident state: 4 (row, col) cells per thread
    float creg[4], hreg[4];
    #pragma unroll
    for (int e = 0; e < 4; e++) { creg[e] = 0.f; hreg[e] = 0.f; }
    #pragma unroll
    for (int e = 0; e < 4; e++) {
        int row = e * 16 + wid;
        g_h16[0][dir][(rBase + row) * UNITS + cbBase + lane] = __float2half(0.f);
    }

    const int wm = wid >> 2;          // 0..3 : 16 rows
    const int wn = wid & 3;           // 0..3 : 32 zcols (gate)
    const int qr = lane >> 2, qc = lane & 3;

    // ldmatrix swizzled base: addr(kb) = C0 ^ (kb*32)
    const int lrow = wm * 16 + (lane & 7) + ((lane >> 3) & 1) * 8;
    const int hi   = lane >> 4;
    const int r7   = lrow & 7;
    uint32_t hA_s = (uint32_t)__cvta_generic_to_shared(hAb);
    const uint32_t C0 = hA_s + (uint32_t)(lrow * 1024 + ((hi ^ (r7 & 1)) * 16) + (r7 >> 1) * 32);

    // staging thread mapping: each thread copies 8 x 16B of one row
    const int srow = tid >> 3, ssub = tid & 7, sr7 = srow & 7;

    // ---- prefetch step 0 (xW + mask) ----
    float xwp[4][4];
    bool  mreg[4];
    {
        int t = dir ? (T_ - 1) : 0;
        #pragma unroll
        for (int e = 0; e < 4; e++) {
            int s = rBase + e * 16 + wid;
            const __half* p = g_xW + ((size_t)s * T_ + t) * NZ + dir * G4 + cbBase + lane;
            #pragma unroll
            for (int g = 0; g < 4; g++) xwp[e][g] = __half2float(p[g * 512]);
            mreg[e] = (x[s * T_ + t] != 0);
        }
    }

    for (int sstep = 0; sstep < T_; sstep++) {
        // group barrier
        __syncthreads();
        if (tid == 0) {
            __threadfence();
            volatile unsigned* genp = &g_bars[gid].gen;
            unsigned gen = *genp;
            if (atomicAdd(&g_bars[gid].cnt, 1u) == GSZ - 1) {
                g_bars[gid].cnt = 0;
                __threadfence();
                *genp = gen + 1;
            } else {
                while (*genp == gen) { __nanosleep(20); }
                __threadfence();
            }
        }
        __syncthreads();

        const int parity = sstep & 1;
        const int t = dir ? (T_ - 1 - sstep) : sstep;
        const __half* h16cur = g_h16[parity][dir];
        __half*       h16nxt = g_h16[parity ^ 1][dir];

        // Stage h tile (64 rows x 512 halves) -> swizzled SMEM
        {
            const __half* src = h16cur + (size_t)(rBase + srow) * UNITS;
            #pragma unroll
            for (int i = 0; i < 8; i++) {
                int u = i * 8 + ssub;
                uint4 v = *(const uint4*)(src + u * 8);
                *(uint4*)(hAb + srow * 1024 + ((u ^ sr7) * 16)) = v;
            }
        }
        __syncthreads();

        // K loop: z = h @ U (fp16 MMA, fp32 accum); warp tile 16x32
        float acc[4][4];
        #pragma unroll
        for (int nt = 0; nt < 4; nt++)
            #pragma unroll
            for (int r = 0; r < 4; r++) acc[nt][r] = 0.f;

        #pragma unroll 8
        for (int kb = 0; kb < 32; kb++) {
            uint32_t a0[4];
            LDSM4(a0, C0 ^ (uint32_t)(kb << 5));
            uint4 B0 = *(const uint4*)&uB[((kb * 8 + wn * 2    ) * 32 + lane) * 4];
            uint4 B1 = *(const uint4*)&uB[((kb * 8 + wn * 2 + 1) * 32 + lane) * 4];
            MMA16816(acc[0], a0, B0.x, B0.y);
            MMA16816(acc[1], a0, B0.z, B0.w);
            MMA16816(acc[2], a0, B1.x, B1.y);
            MMA16816(acc[3], a0, B1.z, B1.w);
        }
        __syncthreads();   // done reading hAb; reuse region for z

        #pragma unroll
        for (int nt = 0; nt < 4; nt++) {
            int row0 = wm * 16 + qr;
            int col  = wn * 32 + nt * 8 + qc * 2;
            *(float2*)&shZ[row0 * ZSTR + col] = make_float2(acc[nt][0], acc[nt][1]);
            *(float2*)&shZ[(row0 + 8) * ZSTR + col] = make_float2(acc[nt][2], acc[nt][3]);
        }
        __syncthreads();

        // Fused gate epilogue; state in registers; write h fp16 for peers
        #pragma unroll
        for (int e = 0; e < 4; e++) {
            int row = e * 16 + wid;
            int hl  = lane;
            float zi = shZ[row * ZSTR +       hl] + xwp[e][0];
            float zf = shZ[row * ZSTR +  32 + hl] + xwp[e][1];
            float zg = shZ[row * ZSTR +  64 + hl] + xwp[e][2];
            float zo = shZ[row * ZSTR +  96 + hl] + xwp[e][3];
            float ig = sigm_fast(zi), fg = sigm_fast(zf);
            float gg = tanh_fast(zg), og = sigm_fast(zo);
            float cnew = fg * creg[e] + ig * gg;
            float hnew = og * tanh_fast(cnew);
            if (mreg[e]) { creg[e] = cnew; hreg[e] = hnew; }
            h16nxt[(rBase + row) * UNITS + cbBase + lane] = __float2half(hreg[e]);
        }

        // Prefetch next step's xW + mask
        if (sstep + 1 < T_) {
            int tn = dir ? (T_ - 2 - sstep) : (sstep + 1);
            #pragma unroll
            for (int e = 0; e < 4; e++) {
                int s = rBase + e * 16 + wid;
                const __half* p = g_xW + ((size_t)s * T_ + tn) * NZ + dir * G4 + cbBase + lane;
                #pragma unroll
                for (int g = 0; g < 4; g++) xwp[e][g] = __half2float(p[g * 512]);
                mreg[e] = (x[s * T_ + tn] != 0);
            }
        }
    }

    // Output straight from registers
    #pragma unroll
    for (int e = 0; e < 4; e++) {
        int s = rBase + e * 16 + wid;
        out[s * 1024 + dir * 512 + cbBase + lane] = hreg[e];
    }
}

// ---------------- launcher -------------------------------------------------
extern "C" void kernel_launch(void* const* d_in, const int* in_sizes, int n_in,
                              void* d_out, int out_size)
{
    const int*   x   = (const int*)  d_in[0];
    const float* emb = (const float*)d_in[1];
    const float* W_f = (const float*)d_in[2];
    const float* U_f = (const float*)d_in[3];
    const float* b_f = (const float*)d_in[4];
    const float* W_b = (const float*)d_in[5];
    const float* U_b = (const float*)d_in[6];
    const float* b_b = (const float*)d_in[7];
    float* out = (float*)d_out;

    cudaFuncSetAttribute(embed_mma,
                         cudaFuncAttributeMaxDynamicSharedMemorySize, 133120);
    cudaFuncSetAttribute(lstm_persist,
                         cudaFuncAttributeMaxDynamicSharedMemorySize, 196608);

    prep_U<<<(2 * 16 * 32768) / 256, 256>>>(U_f, U_b);
    prep_W<<<(32 * 32768) / 256, 256>>>(W_f, W_b);
    embed_mma<<<256, 256, 133120>>>(x, emb, b_f, b_b);
    lstm_persist<<<NCTA, 512, 196608>>>(x, out);
}

// round 13
// speedup vs baseline: 1.4092x; 1.1049x over previous
#include <cuda_runtime.h>
#include <cuda_fp16.h>
#include <math.h>
#include <stdint.h>

// Problem constants
#define T_     128
#define NSEQ   256          // B*S
#define EMBED  512
#define UNITS  512
#define G4     2048         // 4*UNITS
#define NZ     4096         // both directions
#define NCTA   128
#define GSZ    16           // CTAs per dependency group (dir, rb)

// ---------------- scratch (device globals) ---------------------------------
__device__ __half   g_xW[(size_t)NSEQ * T_ * NZ];  // fp16 [s*T+t][4096] fwd|bwd, bias incl
__device__ __half   g_h16[2][2][NSEQ * UNITS];     // fp16 h, [parity][dir]
__device__ uint32_t g_Upk[2 * 16 * 32768];         // fp16 frag-packed U per (dir,cb) slice
__device__ uint32_t g_Wpk[32 * 32768];             // fp16 frag-packed [W_f|W_b]

struct alignas(128) Bar { unsigned cnt; unsigned gen; };
__device__ Bar g_bars[8];                          // one per (dir, rb) group

__device__ __forceinline__ float tanh_fast(float x) {
    float r; asm("tanh.approx.f32 %0, %1;" : "=f"(r) : "f"(x)); return r;
}
__device__ __forceinline__ float sigm_fast(float x) {
    return fmaf(tanh_fast(0.5f * x), 0.5f, 0.5f);
}

// ---------------- pack U into fp16 mma.sync fragment order -----------------
// Slice (dir, cb): B[k][n] = U[k][g*512 + cb*32 + hl], n = g*32+hl (128 zcols).
__global__ __launch_bounds__(256) void prep_U(
    const float* __restrict__ U_f, const float* __restrict__ U_b)
{
    int widx  = blockIdx.x * 256 + threadIdx.x;   // < 2^20
    int word  = widx & 32767;
    int slice = widx >> 15;
    int dir = slice >> 4, cb = slice & 15;
    int kb   = word >> 10;
    int np   = (word >> 7) & 7;
    int lane = (word >> 2) & 31;
    int q    = word & 3;
    int sub = q >> 1, wi = q & 1;
    int qr = lane >> 2, qc = lane & 3;
    int n = (np * 2 + sub) * 8 + qr;
    int k = kb * 16 + wi * 8 + 2 * qc;
    int col = (n >> 5) * 512 + cb * 32 + (n & 31);
    const float* U = dir ? U_b : U_f;
    float lo = U[(size_t)k * G4 + col];
    float hi = U[(size_t)(k + 1) * G4 + col];
    half2 h2 = __floats2half2_rn(lo, hi);
    g_Upk[widx] = *(uint32_t*)&h2;
}

// ---------------- pack [W_f|W_b] into same fragment order ------------------
__global__ __launch_bounds__(256) void prep_W(
    const float* __restrict__ W_f, const float* __restrict__ W_b)
{
    int widx  = blockIdx.x * 256 + threadIdx.x;
    int word  = widx & 32767;
    int nb    = widx >> 15;
    int kb   = word >> 10;
    int np   = (word >> 7) & 7;
    int lane = (word >> 2) & 31;
    int q    = word & 3;
    int sub = q >> 1, wi = q & 1;
    int qr = lane >> 2, qc = lane & 3;
    int nl = (np * 2 + sub) * 8 + qr;
    int k  = kb * 16 + wi * 8 + 2 * qc;
    int c  = nb * 128 + nl;
    const float* W = (c < G4) ? (W_f + c) : (W_b + c - G4);
    float lo = W[(size_t)k * G4];
    float hi = W[(size_t)(k + 1) * G4];
    half2 h2 = __floats2half2_rn(lo, hi);
    g_Wpk[widx] = *(uint32_t*)&h2;
}

// ---------------- MMA helpers ----------------------------------------------
#define MMA16816(d, a, b0v, b1v)                                              \
    asm volatile(                                                             \
        "mma.sync.aligned.m16n8k16.row.col.f32.f16.f16.f32 "                  \
        "{%0,%1,%2,%3},{%4,%5,%6,%7},{%8,%9},{%0,%1,%2,%3};"                  \
        : "+f"(d[0]), "+f"(d[1]), "+f"(d[2]), "+f"(d[3])                      \
        : "r"(a[0]), "r"(a[1]), "r"(a[2]), "r"(a[3]), "r"(b0v), "r"(b1v))

#define LDSM4(r, addr)                                                        \
    asm volatile("ldmatrix.sync.aligned.m8n8.x4.shared.b16 "                  \
                 "{%0,%1,%2,%3}, [%4];"                                       \
                 : "=r"(r[0]), "=r"(r[1]), "=r"(r[2]), "=r"(r[3])             \
                 : "r"(addr))

extern __shared__ char smem_dyn[];

// ---------------- Phase 1: fused gather + fp16 GEMM ------------------------
// 256 CTAs (one per 128-row block) x 256 thr (8 warps). A staged ONCE.
// Warp tile: M=128 (all rows) x N=32 -> B read exactly once per CTA (no
// cross-warp redundancy). Warp w: nb = 2*it + (w>>2), np pair = (w&3)*2.
#define ESTR 520

__global__ __launch_bounds__(256, 1) void embed_mma(
    const int* __restrict__ x, const float* __restrict__ emb,
    const float* __restrict__ b_f, const float* __restrict__ b_b)
{
    __shared__ int ids_s[128];
    __half* hA = (__half*)smem_dyn;                // 128 x ESTR halves

    const int tid  = threadIdx.x;
    const int lane = tid & 31;
    const int wid  = tid >> 5;          // 0..7
    const int qr = lane >> 2, qc = lane & 3;
    const int mBase = blockIdx.x * 128;
    const int wnb = wid >> 2;           // 0..1 : which nb of the pair
    const int np0 = (wid & 3) * 2;      // np pair base (cols [np0*16, np0*16+32))

    if (tid < 128) ids_s[tid] = x[mBase + tid];
    __syncthreads();

    // Stage full A tile once: 128 rows x 512 k, fp32 -> fp16
    {
        int row = tid >> 1, seg = tid & 1;
        const float* src = emb + (size_t)ids_s[row] * EMBED + seg * 256;
        __half* d = hA + row * ESTR + seg * 256;
        #pragma unroll
        for (int i = 0; i < 64; i++) {
            float4 v = *(const float4*)(src + i * 4);
            *(half2*)(d + i * 4)     = __floats2half2_rn(v.x, v.y);
            *(half2*)(d + i * 4 + 2) = __floats2half2_rn(v.z, v.w);
        }
    }
    __syncthreads();

    const int lm_row = (lane & 7) + ((lane >> 3) & 1) * 8;
    const int lm_kh  = (lane >> 4) * 8;
    uint32_t hA_s = (uint32_t)__cvta_generic_to_shared(hA);
    const uint32_t lmbase = hA_s + (uint32_t)((lm_row * ESTR + lm_kh) * 2);
    // addr(mt, kb) = lmbase + mt * (16*ESTR*2) + kb * 32

    for (int it = 0; it < 16; it++) {
        const int nb = it * 2 + wnb;
        const uint32_t* gW = g_Wpk + (size_t)nb * 32768;

        float acc[8][4][4];
        #pragma unroll
        for (int mt = 0; mt < 8; mt++)
            #pragma unroll
            for (int j = 0; j < 4; j++)
                #pragma unroll
                for (int r = 0; r < 4; r++) acc[mt][j][r] = 0.f;

        for (int kb = 0; kb < 32; kb++) {
            uint4 B0 = *(const uint4*)&gW[(((kb * 8 + np0    ) * 32 + lane) << 2)];
            uint4 B1 = *(const uint4*)&gW[(((kb * 8 + np0 + 1) * 32 + lane) << 2)];
            #pragma unroll
            for (int mt = 0; mt < 8; mt++) {
                uint32_t a[4];
                LDSM4(a, lmbase + mt * (16 * ESTR * 2) + kb * 32);
                MMA16816(acc[mt][0], a, B0.x, B0.y);
                MMA16816(acc[mt][1], a, B0.z, B0.w);
                MMA16816(acc[mt][2], a, B1.x, B1.y);
                MMA16816(acc[mt][3], a, B1.z, B1.w);
            }
        }

        // Epilogue: add bias, coalesced half2 stores
        const float* bp = (nb < 16) ? (b_f + nb * 128) : (b_b + nb * 128 - G4);
        #pragma unroll
        for (int mt = 0; mt < 8; mt++) {
            #pragma unroll
            for (int j = 0; j < 4; j++) {
                int row = mBase + mt * 16 + qr;
                int cl  = (np0 * 2 + j) * 8 + qc * 2;   // within nb's 128 cols
                float bx = bp[cl], by = bp[cl + 1];
                half2 lo = __floats2half2_rn(acc[mt][j][0] + bx, acc[mt][j][1] + by);
                half2 hi = __floats2half2_rn(acc[mt][j][2] + bx, acc[mt][j][3] + by);
                *(half2*)&g_xW[(size_t)row * NZ + nb * 128 + cl]       = lo;
                *(half2*)&g_xW[(size_t)(row + 8) * NZ + nb * 128 + cl] = hi;
            }
        }
    }
}

// ---------------- Phase 2: persistent bidirectional LSTM (R7, verbatim) ----
// 128 CTAs x 512 thr. CTA (dir, cb, rb): 64 rows x 128 zcols.
// Warp (wm 0..3, wn 0..3): 16 rows x 32 zcols (wn = gate). 16-CTA group sync.
#define ZSTR 132   // z exchange row stride in floats

__global__ __launch_bounds__(512, 1) void lstm_persist(
    const int* __restrict__ x, float* __restrict__ out)
{
    uint32_t* uB  = (uint32_t*)smem_dyn;           // 128 KB
    char*     hAb = smem_dyn + 131072;             // 64 KB swizzled A staging
    float*    shZ = (float*)(smem_dyn + 131072);   // alias (post-sync)

    const int tid  = threadIdx.x;
    const int lane = tid & 31;
    const int wid  = tid >> 5;                     // 0..15
    const int bid  = blockIdx.x;
    const int dir  = bid >> 6;
    const int cb   = (bid >> 2) & 15;
    const int rb   = bid & 3;
    const int gid  = dir * 4 + rb;
    const int rBase  = rb * 64;
    const int cbBase = cb * 32;

    // Load U slice once (resident for all steps)
    {
        const uint4* src = (const uint4*)(g_Upk + (size_t)(dir * 16 + cb) * 32768);
        uint4* dst = (uint4*)uB;
        #pragma unroll
        for (int i = 0; i < 16; i++) dst[i * 512 + tid] = src[i * 512 + tid];
    }

    // Register-resident state: 4 (row, col) cells per thread
    float creg[4], hreg[4];
    #pragma unroll
    for (int e = 0; e < 4; e++) { creg[e] = 0.f; hreg[e] = 0.f; }
    #pragma unroll
    for (int e = 0; e < 4; e++) {
        int row = e * 16 + wid;
        g_h16[0][dir][(rBase + row) * UNITS + cbBase + lane] = __float2half(0.f);
    }

    const int wm = wid >> 2;          // 0..3 : 16 rows
    const int wn = wid & 3;           // 0..3 : 32 zcols (gate)
    const int qr = lane >> 2, qc = lane & 3;

    // ldmatrix swizzled base: addr(kb) = C0 ^ (kb*32)
    const int lrow = wm * 16 + (lane & 7) + ((lane >> 3) & 1) * 8;
    const int hi   = lane >> 4;
    const int r7   = lrow & 7;
    uint32_t hA_s = (uint32_t)__cvta_generic_to_shared(hAb);
    const uint32_t C0 = hA_s + (uint32_t)(lrow * 1024 + ((hi ^ (r7 & 1)) * 16) + (r7 >> 1) * 32);

    // staging thread mapping: each thread copies 8 x 16B of one row
    const int srow = tid >> 3, ssub = tid & 7, sr7 = srow & 7;

    // ---- prefetch step 0 (xW + mask) ----
    float xwp[4][4];
    bool  mreg[4];
    {
        int t = dir ? (T_ - 1) : 0;
        #pragma unroll
        for (int e = 0; e < 4; e++) {
            int s = rBase + e * 16 + wid;
            const __half* p = g_xW + ((size_t)s * T_ + t) * NZ + dir * G4 + cbBase + lane;
            #pragma unroll
            for (int g = 0; g < 4; g++) xwp[e][g] = __half2float(p[g * 512]);
            mreg[e] = (x[s * T_ + t] != 0);
        }
    }

    for (int sstep = 0; sstep < T_; sstep++) {
        // group barrier
        __syncthreads();
        if (tid == 0) {
            __threadfence();
            volatile unsigned* genp = &g_bars[gid].gen;
            unsigned gen = *genp;
            if (atomicAdd(&g_bars[gid].cnt, 1u) == GSZ - 1) {
                g_bars[gid].cnt = 0;
                __threadfence();
                *genp = gen + 1;
            } else {
                while (*genp == gen) { __nanosleep(20); }
                __threadfence();
            }
        }
        __syncthreads();

        const int parity = sstep & 1;
        const int t = dir ? (T_ - 1 - sstep) : sstep;
        const __half* h16cur = g_h16[parity][dir];
        __half*       h16nxt = g_h16[parity ^ 1][dir];

        // Stage h tile (64 rows x 512 halves) -> swizzled SMEM
        {
            const __half* src = h16cur + (size_t)(rBase + srow) * UNITS;
            #pragma unroll
            for (int i = 0; i < 8; i++) {
                int u = i * 8 + ssub;
                uint4 v = *(const uint4*)(src + u * 8);
                *(uint4*)(hAb + srow * 1024 + ((u ^ sr7) * 16)) = v;
            }
        }
        __syncthreads();

        // K loop: z = h @ U (fp16 MMA, fp32 accum); warp tile 16x32
        float acc[4][4];
        #pragma unroll
        for (int nt = 0; nt < 4; nt++)
            #pragma unroll
            for (int r = 0; r < 4; r++) acc[nt][r] = 0.f;

        #pragma unroll 8
        for (int kb = 0; kb < 32; kb++) {
            uint32_t a0[4];
            LDSM4(a0, C0 ^ (uint32_t)(kb << 5));
            uint4 B0 = *(const uint4*)&uB[((kb * 8 + wn * 2    ) * 32 + lane) * 4];
            uint4 B1 = *(const uint4*)&uB[((kb * 8 + wn * 2 + 1) * 32 + lane) * 4];
            MMA16816(acc[0], a0, B0.x, B0.y);
            MMA16816(acc[1], a0, B0.z, B0.w);
            MMA16816(acc[2], a0, B1.x, B1.y);
            MMA16816(acc[3], a0, B1.z, B1.w);
        }
        __syncthreads();   // done reading hAb; reuse region for z

        #pragma unroll
        for (int nt = 0; nt < 4; nt++) {
            int row0 = wm * 16 + qr;
            int col  = wn * 32 + nt * 8 + qc * 2;
            *(float2*)&shZ[row0 * ZSTR + col] = make_float2(acc[nt][0], acc[nt][1]);
            *(float2*)&shZ[(row0 + 8) * ZSTR + col] = make_float2(acc[nt][2], acc[nt][3]);
        }
        __syncthreads();

        // Fused gate epilogue; state in registers; write h fp16 for peers
        #pragma unroll
        for (int e = 0; e < 4; e++) {
            int row = e * 16 + wid;
            int hl  = lane;
            float zi = shZ[row * ZSTR +       hl] + xwp[e][0];
            float zf = shZ[row * ZSTR +  32 + hl] + xwp[e][1];
            float zg = shZ[row * ZSTR +  64 + hl] + xwp[e][2];
            float zo = shZ[row * ZSTR +  96 + hl] + xwp[e][3];
            float ig = sigm_fast(zi), fg = sigm_fast(zf);
            float gg = tanh_fast(zg), og = sigm_fast(zo);
            float cnew = fg * creg[e] + ig * gg;
            float hnew = og * tanh_fast(cnew);
            if (mreg[e]) { creg[e] = cnew; hreg[e] = hnew; }
            h16nxt[(rBase + row) * UNITS + cbBase + lane] = __float2half(hreg[e]);
        }

        // Prefetch next step's xW + mask
        if (sstep + 1 < T_) {
            int tn = dir ? (T_ - 2 - sstep) : (sstep + 1);
            #pragma unroll
            for (int e = 0; e < 4; e++) {
                int s = rBase + e * 16 + wid;
                const __half* p = g_xW + ((size_t)s * T_ + tn) * NZ + dir * G4 + cbBase + lane;
                #pragma unroll
                for (int g = 0; g < 4; g++) xwp[e][g] = __half2float(p[g * 512]);
                mreg[e] = (x[s * T_ + tn] != 0);
            }
        }
    }

    // Output straight from registers
    #pragma unroll
    for (int e = 0; e < 4; e++) {
        int s = rBase + e * 16 + wid;
        out[s * 1024 + dir * 512 + cbBase + lane] = hreg[e];
    }
}

// ---------------- launcher -------------------------------------------------
extern "C" void kernel_launch(void* const* d_in, const int* in_sizes, int n_in,
                              void* d_out, int out_size)
{
    const int*   x   = (const int*)  d_in[0];
    const float* emb = (const float*)d_in[1];
    const float* W_f = (const float*)d_in[2];
    const float* U_f = (const float*)d_in[3];
    const float* b_f = (const float*)d_in[4];
    const float* W_b = (const float*)d_in[5];
    const float* U_b = (const float*)d_in[6];
    const float* b_b = (const float*)d_in[7];
    float* out = (float*)d_out;

    cudaFuncSetAttribute(embed_mma,
                         cudaFuncAttributeMaxDynamicSharedMemorySize, 133120);
    cudaFuncSetAttribute(lstm_persist,
                         cudaFuncAttributeMaxDynamicSharedMemorySize, 196608);

    prep_U<<<(2 * 16 * 32768) / 256, 256>>>(U_f, U_b);
    prep_W<<<(32 * 32768) / 256, 256>>>(W_f, W_b);
    embed_mma<<<256, 256, 133120>>>(x, emb, b_f, b_b);
    lstm_persist<<<NCTA, 512, 196608>>>(x, out);
}